// round 6
// baseline (speedup 1.0000x reference)
#include <cuda_runtime.h>
#include <math.h>

#define SEQ  2048
#define HID  2048
#define NH   16
#define HD   128
#define RD   64
#define DT   192        // HD + RD
#define KVC  512
#define QC   1024

// ---------------- scratch (device globals: allocation-free) ----------------
__device__ float g_kvc[SEQ * KVC];
__device__ float g_qc [SEQ * QC];
__device__ float g_K  [SEQ * NH * DT];
__device__ float g_Q  [SEQ * NH * DT];
__device__ float g_V  [SEQ * NH * HD];
__device__ float g_ctx[SEQ * NH * HD];

// ---------------- helpers ----------------
__device__ __forceinline__ float f2tf(float x) {
    unsigned r;
    asm("cvt.rna.tf32.f32 %0, %1;" : "=r"(r) : "f"(x));
    return __uint_as_float(r);
}

__device__ __forceinline__ void mma_tf32(float* c, const unsigned* a, const unsigned* b) {
    asm volatile(
        "mma.sync.aligned.m16n8k8.row.col.f32.tf32.tf32.f32 "
        "{%0,%1,%2,%3}, {%4,%5,%6,%7}, {%8,%9}, {%0,%1,%2,%3};\n"
        : "+f"(c[0]), "+f"(c[1]), "+f"(c[2]), "+f"(c[3])
        : "r"(a[0]), "r"(a[1]), "r"(a[2]), "r"(a[3]),
          "r"(b[0]), "r"(b[1]));
}

__device__ __forceinline__ void ldsm4(unsigned* r, const void* p) {
    unsigned addr = (unsigned)__cvta_generic_to_shared(p);
    asm volatile("ldmatrix.sync.aligned.m8n8.x4.shared.b16 {%0,%1,%2,%3}, [%4];"
        : "=r"(r[0]), "=r"(r[1]), "=r"(r[2]), "=r"(r[3]) : "r"(addr));
}

// ---------------------------------------------------------------------------
// Tensor-core GEMM: C[M,N] = A[M,K] @ B[N,K]^T + bias (row-major, K contig).
// 128x128 CTA, 128 threads, 4 warps (warp tile 64x64), KT=16, double-buffered
// smem (one __syncthreads per k-tile), tf32 rounding done at STS time.
// EPI: 0 plain, 1 split [s][h][192]@0, 2 RoPE [s][h][192]@128
// RND: round outputs to tf32 (for intermediates consumed by later mma).
// ---------------------------------------------------------------------------
template<int EPI, bool RND>
__global__ void __launch_bounds__(128)
gemm_tc(const float* __restrict__ A, const float* __restrict__ B,
        const float* __restrict__ bias, float* __restrict__ C,
        int N, int K)
{
    __shared__ float As[2][128][20];
    __shared__ float Bs[2][128][20];

    const int tid  = threadIdx.x;
    const int warp = tid >> 5, lane = tid & 31;
    const int g    = lane >> 2, tig = lane & 3;
    const int wm   = warp >> 1, wn  = warp & 1;      // 2x2 warps of 64x64
    const int bm   = blockIdx.y * 128, bn = blockIdx.x * 128;

    // loader: each of 128 threads owns A row tid and B row tid (16 floats each)
    const float* Ap = A + (size_t)(bm + tid) * K;
    const float* Bp = B + (size_t)(bn + tid) * K;

    float4 sa[4], sb[4];
#pragma unroll
    for (int q = 0; q < 4; q++) {
        sa[q] = *(const float4*)(Ap + q * 4);
        sb[q] = *(const float4*)(Bp + q * 4);
    }

    float acc[4][8][4];
#pragma unroll
    for (int mi = 0; mi < 4; mi++)
#pragma unroll
        for (int ni = 0; ni < 8; ni++)
#pragma unroll
            for (int e = 0; e < 4; e++) acc[mi][ni][e] = 0.f;

    // ldmatrix lane addressing
    const int a_row = (lane & 15);
    const int a_k   = 4 * (lane >> 4);
    const int b_row = ((lane >> 4) << 3) + (lane & 7);
    const int b_k   = 4 * ((lane >> 3) & 1);

    // prologue: round + store tile 0 into buffer 0
#pragma unroll
    for (int q = 0; q < 4; q++) {
        *(float4*)&As[0][tid][q * 4] =
            make_float4(f2tf(sa[q].x), f2tf(sa[q].y), f2tf(sa[q].z), f2tf(sa[q].w));
        *(float4*)&Bs[0][tid][q * 4] =
            make_float4(f2tf(sb[q].x), f2tf(sb[q].y), f2tf(sb[q].z), f2tf(sb[q].w));
    }
    __syncthreads();

    const int T = K >> 4;
    for (int t = 0; t < T; t++) {
        const int cur = t & 1, nxt = cur ^ 1;
        if (t + 1 < T) {
            const int ko = (t + 1) << 4;
#pragma unroll
            for (int q = 0; q < 4; q++) {
                sa[q] = *(const float4*)(Ap + ko + q * 4);
                sb[q] = *(const float4*)(Bp + ko + q * 4);
            }
        }
        // compute on buffer `cur`
#pragma unroll
        for (int ks = 0; ks < 2; ks++) {
            const int k8 = ks * 8;
            unsigned a[4][4];
#pragma unroll
            for (int mi = 0; mi < 4; mi++)
                ldsm4(a[mi], &As[cur][wm * 64 + mi * 16 + a_row][k8 + a_k]);
            unsigned b[8][2];
#pragma unroll
            for (int nip = 0; nip < 4; nip++) {
                unsigned t4[4];
                ldsm4(t4, &Bs[cur][wn * 64 + nip * 16 + b_row][k8 + b_k]);
                b[2 * nip][0]     = t4[0];
                b[2 * nip][1]     = t4[1];
                b[2 * nip + 1][0] = t4[2];
                b[2 * nip + 1][1] = t4[3];
            }
#pragma unroll
            for (int mi = 0; mi < 4; mi++)
#pragma unroll
                for (int ni = 0; ni < 8; ni++)
                    mma_tf32(acc[mi][ni], a[mi], b[ni]);
        }
        if (t + 1 < T) {
#pragma unroll
            for (int q = 0; q < 4; q++) {
                *(float4*)&As[nxt][tid][q * 4] =
                    make_float4(f2tf(sa[q].x), f2tf(sa[q].y), f2tf(sa[q].z), f2tf(sa[q].w));
                *(float4*)&Bs[nxt][tid][q * 4] =
                    make_float4(f2tf(sb[q].x), f2tf(sb[q].y), f2tf(sb[q].z), f2tf(sb[q].w));
            }
        }
        __syncthreads();
    }

    // ---------------- epilogue ----------------
#pragma unroll
    for (int mi = 0; mi < 4; mi++) {
        const int r0 = bm + wm * 64 + mi * 16 + g;
#pragma unroll
        for (int ni = 0; ni < 8; ni++) {
            const int c0 = bn + wn * 64 + ni * 8 + 2 * tig;
            const float b0 = bias[c0], b1 = bias[c0 + 1];
            float v00 = acc[mi][ni][0] + b0, v01 = acc[mi][ni][1] + b1;
            float v10 = acc[mi][ni][2] + b0, v11 = acc[mi][ni][3] + b1;
            if (EPI == 2) {
                const int hh = c0 >> 6;
                const int rr = c0 & 63;
                const int jj = rr >> 1;
                float fr = __expf(-(float)jj * 0.28782313663258307f); // ln(1e4)/32
                float sn, cs;
                sincosf((float)hh * fr, &sn, &cs);
                float w00 = v00 * cs - v01 * sn, w01 = v00 * sn + v01 * cs;
                float w10 = v10 * cs - v11 * sn, w11 = v10 * sn + v11 * cs;
                if (RND) { w00 = f2tf(w00); w01 = f2tf(w01); w10 = f2tf(w10); w11 = f2tf(w11); }
                float* d0 = C + ((size_t)r0 * NH + hh) * DT + HD + rr;
                float* d1 = C + ((size_t)(r0 + 8) * NH + hh) * DT + HD + rr;
                *(float2*)d0 = make_float2(w00, w01);
                *(float2*)d1 = make_float2(w10, w11);
            } else {
                if (RND) { v00 = f2tf(v00); v01 = f2tf(v01); v10 = f2tf(v10); v11 = f2tf(v11); }
                if (EPI == 1) {
                    const int hh = c0 >> 7, dd = c0 & 127;
                    float* d0 = C + ((size_t)r0 * NH + hh) * DT + dd;
                    float* d1 = C + ((size_t)(r0 + 8) * NH + hh) * DT + dd;
                    *(float2*)d0 = make_float2(v00, v01);
                    *(float2*)d1 = make_float2(v10, v11);
                } else {
                    *(float2*)&C[(size_t)r0 * N + c0]       = make_float2(v00, v01);
                    *(float2*)&C[(size_t)(r0 + 8) * N + c0] = make_float2(v10, v11);
                }
            }
        }
    }
}

// ---------------------------------------------------------------------------
// Flash attention, tf32 mma + ldmatrix. Block = (head, 128 q-rows), 256 thr.
// Q/K/V pre-rounded to tf32 by producer epilogues (no cvt here).
// V transposed into smem with XOR swizzle for ldmatrix B-fragments.
// ---------------------------------------------------------------------------
#define QS_LD 196
#define KS_LD 196
#define VLD   68
#define PS_LD 68
#define ATTN_SM_FLOATS (128*QS_LD + 64*KS_LD + 128*VLD + 128*PS_LD)
#define ATTN_SM_BYTES  (ATTN_SM_FLOATS * 4)

__device__ __forceinline__ int vst_off(int d, int k) {
    return d * VLD + ((((k >> 2) ^ ((d >> 3) & 7))) << 2) + (k & 3);
}

__global__ void __launch_bounds__(256)
attn_tc(const float* __restrict__ Qg, const float* __restrict__ Kg,
        const float* __restrict__ Vg, float* __restrict__ ctxg)
{
    extern __shared__ float sm[];
    float* Qs  = sm;                       // [128][196]
    float* Ks  = Qs + 128 * QS_LD;         // [64][196]
    float* Vst = Ks + 64 * KS_LD;          // [128][68]  (d-major, swizzled k)
    float* Ps  = Vst + 128 * VLD;          // [128][68]

    const int tid  = threadIdx.x;
    const int warp = tid >> 5, lane = tid & 31;
    const int g    = lane >> 2, tig = lane & 3;
    const int h    = blockIdx.y;
    const int q0   = blockIdx.x * 128;

    const int a_row = (lane & 15);
    const int a_k   = 4 * (lane >> 4);
    const int b_row = ((lane >> 4) << 3) + (lane & 7);
    const int b_k   = 4 * ((lane >> 3) & 1);
    const int b_ks  = (lane >> 3) & 1;     // k8-half select for swizzled V

    // ---- load Q tile (raw copy; already tf32) ----
#pragma unroll
    for (int i = 0; i < 24; i++) {
        int idx = tid + 256 * i;
        int row = idx / 48, f4 = idx % 48;
        *(float4*)&Qs[row * QS_LD + f4 * 4] =
            *(const float4*)(Qg + (size_t)(q0 + row) * (NH * DT) + h * DT + f4 * 4);
    }

    float m_[2] = {-1e30f, -1e30f}, l_[2] = {0.f, 0.f};
    float o[16][4];
#pragma unroll
    for (int ni = 0; ni < 16; ni++)
#pragma unroll
        for (int e = 0; e < 4; e++) o[ni][e] = 0.f;

    const float SCALE = 0.07216878364870323f;   // 1/sqrt(192)
    const int rw = warp * 16;
    const int prow = rw + g;

    for (int kt = 0; kt < SEQ / 64; kt++) {
        const int kbase = kt * 64;
        // ---- K tile ----
#pragma unroll
        for (int i = 0; i < 12; i++) {
            int idx = tid + 256 * i;
            int row = idx / 48, f4 = idx % 48;
            *(float4*)&Ks[row * KS_LD + f4 * 4] =
                *(const float4*)(Kg + (size_t)(kbase + row) * (NH * DT) + h * DT + f4 * 4);
        }
        // ---- V tile, transposed with swizzle ----
#pragma unroll
        for (int i = 0; i < 8; i++) {
            int idx = tid + 256 * i;
            int krow = idx >> 5, d4 = (idx & 31) << 2;
            float4 v = *(const float4*)(Vg + (size_t)(kbase + krow) * (NH * HD) + h * HD + d4);
            Vst[vst_off(d4 + 0, krow)] = v.x;
            Vst[vst_off(d4 + 1, krow)] = v.y;
            Vst[vst_off(d4 + 2, krow)] = v.z;
            Vst[vst_off(d4 + 3, krow)] = v.w;
        }
        __syncthreads();

        // ---- S = Q K^T : warp rows rw..rw+15, cols 0..63 ----
        float s[8][4];
#pragma unroll
        for (int ni = 0; ni < 8; ni++)
#pragma unroll
            for (int e = 0; e < 4; e++) s[ni][e] = 0.f;

#pragma unroll
        for (int kk = 0; kk < 24; kk++) {
            const int k8 = kk * 8;
            unsigned a[4];
            ldsm4(a, &Qs[(rw + a_row) * QS_LD + k8 + a_k]);
#pragma unroll
            for (int nip = 0; nip < 4; nip++) {
                unsigned b[4];
                ldsm4(b, &Ks[(nip * 16 + b_row) * KS_LD + k8 + b_k]);
                mma_tf32(s[2 * nip], a, b);
                mma_tf32(s[2 * nip + 1], a, b + 2);
            }
        }

        // ---- online softmax (rows prow / prow+8) ----
        float tm0 = -1e30f, tm1 = -1e30f;
#pragma unroll
        for (int ni = 0; ni < 8; ni++) {
#pragma unroll
            for (int e = 0; e < 4; e++) s[ni][e] *= SCALE;
            tm0 = fmaxf(tm0, fmaxf(s[ni][0], s[ni][1]));
            tm1 = fmaxf(tm1, fmaxf(s[ni][2], s[ni][3]));
        }
        tm0 = fmaxf(tm0, __shfl_xor_sync(0xffffffffu, tm0, 1, 4));
        tm0 = fmaxf(tm0, __shfl_xor_sync(0xffffffffu, tm0, 2, 4));
        tm1 = fmaxf(tm1, __shfl_xor_sync(0xffffffffu, tm1, 1, 4));
        tm1 = fmaxf(tm1, __shfl_xor_sync(0xffffffffu, tm1, 2, 4));

        float mn0 = fmaxf(m_[0], tm0), mn1 = fmaxf(m_[1], tm1);
        float corr0 = __expf(m_[0] - mn0), corr1 = __expf(m_[1] - mn1);
        m_[0] = mn0; m_[1] = mn1;

        float rs0 = 0.f, rs1 = 0.f;
#pragma unroll
        for (int ni = 0; ni < 8; ni++) {
            s[ni][0] = __expf(s[ni][0] - mn0);
            s[ni][1] = __expf(s[ni][1] - mn0);
            s[ni][2] = __expf(s[ni][2] - mn1);
            s[ni][3] = __expf(s[ni][3] - mn1);
            rs0 += s[ni][0] + s[ni][1];
            rs1 += s[ni][2] + s[ni][3];
        }
        rs0 += __shfl_xor_sync(0xffffffffu, rs0, 1, 4);
        rs0 += __shfl_xor_sync(0xffffffffu, rs0, 2, 4);
        rs1 += __shfl_xor_sync(0xffffffffu, rs1, 1, 4);
        rs1 += __shfl_xor_sync(0xffffffffu, rs1, 2, 4);
        l_[0] = l_[0] * corr0 + rs0;
        l_[1] = l_[1] * corr1 + rs1;

        // ---- stage P (tf32, warp-local rows), rescale ctx ----
#pragma unroll
        for (int ni = 0; ni < 8; ni++) {
            *(float2*)&Ps[prow * PS_LD + ni * 8 + 2 * tig] =
                make_float2(f2tf(s[ni][0]), f2tf(s[ni][1]));
            *(float2*)&Ps[(prow + 8) * PS_LD + ni * 8 + 2 * tig] =
                make_float2(f2tf(s[ni][2]), f2tf(s[ni][3]));
        }
#pragma unroll
        for (int ni = 0; ni < 16; ni++) {
            o[ni][0] *= corr0; o[ni][1] *= corr0;
            o[ni][2] *= corr1; o[ni][3] *= corr1;
        }
        __syncwarp();

        // ---- ctx += P @ V (A from Ps, B from swizzled Vst) ----
#pragma unroll
        for (int ks = 0; ks < 8; ks++) {
            unsigned a[4];
            ldsm4(a, &Ps[(rw + a_row) * PS_LD + ks * 8 + a_k]);
#pragma unroll
            for (int nip = 0; nip < 8; nip++) {
                const int d = nip * 16 + b_row;
                const int kunit = 2 * ks + b_ks;
                unsigned b[4];
                ldsm4(b, &Vst[d * VLD + (((kunit ^ ((d >> 3) & 7))) << 2)]);
                mma_tf32(o[2 * nip], a, b);
                mma_tf32(o[2 * nip + 1], a, b + 2);
            }
        }
        __syncthreads();
    }

    // ---- finalize & store (raw fp32; consumer GEMM rounds) ----
    const float inv0 = 1.0f / l_[0], inv1 = 1.0f / l_[1];
    const int r0 = q0 + rw + g;
#pragma unroll
    for (int ni = 0; ni < 16; ni++) {
        const int col = ni * 8 + 2 * tig;
        *(float2*)&ctxg[(size_t)r0 * (NH * HD) + h * HD + col] =
            make_float2(o[ni][0] * inv0, o[ni][1] * inv0);
        *(float2*)&ctxg[(size_t)(r0 + 8) * (NH * HD) + h * HD + col] =
            make_float2(o[ni][2] * inv1, o[ni][3] * inv1);
    }
}

// ---------------------------------------------------------------------------
extern "C" void kernel_launch(void* const* d_in, const int* in_sizes, int n_in,
                              void* d_out, int out_size)
{
    (void)in_sizes; (void)n_in; (void)out_size;
    const float* x   = (const float*)d_in[0];
    const float* kdw = (const float*)d_in[1];
    const float* kdb = (const float*)d_in[2];
    const float* kuw = (const float*)d_in[3];
    const float* kub = (const float*)d_in[4];
    const float* vuw = (const float*)d_in[5];
    const float* vub = (const float*)d_in[6];
    const float* krw = (const float*)d_in[7];
    const float* krb = (const float*)d_in[8];
    const float* qdw = (const float*)d_in[9];
    const float* qdb = (const float*)d_in[10];
    const float* quw = (const float*)d_in[11];
    const float* qub = (const float*)d_in[12];
    const float* qrw = (const float*)d_in[13];
    const float* qrb = (const float*)d_in[14];
    const float* ow  = (const float*)d_in[15];
    const float* ob  = (const float*)d_in[16];
    float* out = (float*)d_out;

    float *kvc, *qc, *Kb, *Qb, *Vb, *ctx;
    cudaGetSymbolAddress((void**)&kvc, g_kvc);
    cudaGetSymbolAddress((void**)&qc,  g_qc);
    cudaGetSymbolAddress((void**)&Kb,  g_K);
    cudaGetSymbolAddress((void**)&Qb,  g_Q);
    cudaGetSymbolAddress((void**)&Vb,  g_V);
    cudaGetSymbolAddress((void**)&ctx, g_ctx);

    dim3 blk(128);

    gemm_tc<0, true ><<<dim3(KVC / 128, SEQ / 128), blk>>>(x, kdw, kdb, kvc, KVC, HID);
    gemm_tc<0, true ><<<dim3(QC / 128, SEQ / 128), blk>>>(x, qdw, qdb, qc, QC, HID);
    gemm_tc<1, true ><<<dim3(2048 / 128, SEQ / 128), blk>>>(kvc, kuw, kub, Kb, 2048, KVC);
    gemm_tc<0, true ><<<dim3(2048 / 128, SEQ / 128), blk>>>(kvc, vuw, vub, Vb, 2048, KVC);
    gemm_tc<2, true ><<<dim3(1024 / 128, SEQ / 128), blk>>>(kvc, krw, krb, Kb, 1024, KVC);
    gemm_tc<1, true ><<<dim3(2048 / 128, SEQ / 128), blk>>>(qc, quw, qub, Qb, 2048, QC);
    gemm_tc<2, true ><<<dim3(1024 / 128, SEQ / 128), blk>>>(qc, qrw, qrb, Qb, 1024, QC);

    cudaFuncSetAttribute(attn_tc, cudaFuncAttributeMaxDynamicSharedMemorySize,
                         ATTN_SM_BYTES);
    attn_tc<<<dim3(SEQ / 128, NH), dim3(256), ATTN_SM_BYTES>>>(Qb, Kb, Vb, ctx);

    gemm_tc<0, false><<<dim3(2048 / 128, SEQ / 128), blk>>>(ctx, ow, ob, out, HID, 2048);
}

// round 12
// speedup vs baseline: 1.5259x; 1.5259x over previous
#include <cuda_runtime.h>
#include <cuda_fp16.h>
#include <math.h>
#include <stdint.h>

#define SEQ  2048
#define HID  2048
#define NH   16
#define HD   128
#define RD   64
#define DT   192        // HD + RD
#define KVC  512
#define QC   1024

// static scales keeping fp16-stored tensors in normal range
#define SCL_KQ 16.0f     // K and Q each scaled by 16
#define SCL_V  1024.0f   // V (and hence ctx) scaled by 1024

// ---------------- scratch (device globals: allocation-free) ----------------
__device__ __half g_kvc[SEQ * KVC];
__device__ __half g_qc [SEQ * QC];
__device__ __half g_K  [SEQ * NH * DT];
__device__ __half g_Q  [SEQ * NH * DT];
__device__ __half g_V  [SEQ * NH * HD];
__device__ __half g_ctx[SEQ * NH * HD];

// ---------------- helpers ----------------
__device__ __forceinline__ unsigned packh2(float a, float b) {
    __half2 h = __floats2half2_rn(a, b);
    return *(unsigned*)&h;
}
__device__ __forceinline__ void sth2(__half* p, float a, float b) {
    *(__half2*)p = __floats2half2_rn(a, b);
}

__device__ __forceinline__ void mma_f16(float* c, const unsigned* a, const unsigned* b) {
    asm volatile(
        "mma.sync.aligned.m16n8k16.row.col.f32.f16.f16.f32 "
        "{%0,%1,%2,%3}, {%4,%5,%6,%7}, {%8,%9}, {%0,%1,%2,%3};\n"
        : "+f"(c[0]), "+f"(c[1]), "+f"(c[2]), "+f"(c[3])
        : "r"(a[0]), "r"(a[1]), "r"(a[2]), "r"(a[3]),
          "r"(b[0]), "r"(b[1]));
}

__device__ __forceinline__ void ldsm4(unsigned* r, const void* p) {
    unsigned addr = (unsigned)__cvta_generic_to_shared(p);
    asm volatile("ldmatrix.sync.aligned.m8n8.x4.shared.b16 {%0,%1,%2,%3}, [%4];"
        : "=r"(r[0]), "=r"(r[1]), "=r"(r[2]), "=r"(r[3]) : "r"(addr));
}

// ---------------------------------------------------------------------------
// fp16 tensor-core GEMM: C = (A @ B^T * iscl + bias) * oscl (row-major).
// 128x128 CTA, 256 threads, 8 warps (warp tile 32x64), KT=32 halves,
// ping-pong smem, one __syncthreads per k-tile, ldmatrix fragments.
// EPI: 0 plain, 1 split [s][h][192]@0, 2 RoPE [s][h][192]@128
// ---------------------------------------------------------------------------
#define GLD 40   // smem row stride in halves (80B: conflict-free ldmatrix)

template<int EPI, bool AHALF, bool OUTH>
__global__ void __launch_bounds__(256)
gemm_h(const void* __restrict__ Av, const float* __restrict__ B,
       const float* __restrict__ bias, void* __restrict__ Cv,
       int N, int K, float iscl, float oscl)
{
    __shared__ __half As[2][128][GLD];
    __shared__ __half Bs[2][128][GLD];

    const int tid  = threadIdx.x;
    const int warp = tid >> 5, lane = tid & 31;
    const int g    = lane >> 2, tig = lane & 3;
    const int wm   = warp >> 1, wn  = warp & 1;     // 4x2 warps: 32x64 tiles
    const int bm   = blockIdx.y * 128, bn = blockIdx.x * 128;

    // loader: 2 threads per row, 16 halves each
    const int lrow = tid >> 1, lh = (tid & 1) * 16;
    const float*  Bp  = B + (size_t)(bn + lrow) * K + lh;
    const float*  Apf = nullptr;
    const __half* Aph = nullptr;
    if constexpr (AHALF) Aph = (const __half*)Av + (size_t)(bm + lrow) * K + lh;
    else                 Apf = (const float*)Av + (size_t)(bm + lrow) * K + lh;

    uint4 ra[2], rb[2];
    auto loadA = [&](int ko) {
        if constexpr (AHALF) {
            ra[0] = *(const uint4*)(Aph + ko);
            ra[1] = *(const uint4*)(Aph + ko + 8);
        } else {
            float4 f0 = *(const float4*)(Apf + ko);
            float4 f1 = *(const float4*)(Apf + ko + 4);
            float4 f2 = *(const float4*)(Apf + ko + 8);
            float4 f3 = *(const float4*)(Apf + ko + 12);
            ra[0] = make_uint4(packh2(f0.x, f0.y), packh2(f0.z, f0.w),
                               packh2(f1.x, f1.y), packh2(f1.z, f1.w));
            ra[1] = make_uint4(packh2(f2.x, f2.y), packh2(f2.z, f2.w),
                               packh2(f3.x, f3.y), packh2(f3.z, f3.w));
        }
    };
    auto loadB = [&](int ko) {
        float4 f0 = *(const float4*)(Bp + ko);
        float4 f1 = *(const float4*)(Bp + ko + 4);
        float4 f2 = *(const float4*)(Bp + ko + 8);
        float4 f3 = *(const float4*)(Bp + ko + 12);
        rb[0] = make_uint4(packh2(f0.x, f0.y), packh2(f0.z, f0.w),
                           packh2(f1.x, f1.y), packh2(f1.z, f1.w));
        rb[1] = make_uint4(packh2(f2.x, f2.y), packh2(f2.z, f2.w),
                           packh2(f3.x, f3.y), packh2(f3.z, f3.w));
    };

    float acc[2][8][4];
#pragma unroll
    for (int mi = 0; mi < 2; mi++)
#pragma unroll
        for (int ni = 0; ni < 8; ni++)
#pragma unroll
            for (int e = 0; e < 4; e++) acc[mi][ni][e] = 0.f;

    // ldmatrix lane addressing
    const int a_row = lane & 15;
    const int a_c   = 8 * (lane >> 4);
    const int b_row = ((lane >> 4) << 3) + (lane & 7);
    const int b_c   = 8 * ((lane >> 3) & 1);

    // prologue: stage 0 -> buffer 0
    loadA(0); loadB(0);
    *(uint4*)&As[0][lrow][lh]     = ra[0];
    *(uint4*)&As[0][lrow][lh + 8] = ra[1];
    *(uint4*)&Bs[0][lrow][lh]     = rb[0];
    *(uint4*)&Bs[0][lrow][lh + 8] = rb[1];
    __syncthreads();

    const int T = K >> 5;
    for (int t = 0; t < T; t++) {
        const int cur = t & 1, nxt = cur ^ 1;
        if (t + 1 < T) { loadA((t + 1) << 5); loadB((t + 1) << 5); }

#pragma unroll
        for (int ks = 0; ks < 2; ks++) {
            const int k16 = ks * 16;
            unsigned a[2][4];
#pragma unroll
            for (int mi = 0; mi < 2; mi++)
                ldsm4(a[mi], &As[cur][wm * 32 + mi * 16 + a_row][k16 + a_c]);
#pragma unroll
            for (int np = 0; np < 4; np++) {
                unsigned bt[4];
                ldsm4(bt, &Bs[cur][wn * 64 + np * 16 + b_row][k16 + b_c]);
#pragma unroll
                for (int mi = 0; mi < 2; mi++) {
                    mma_f16(acc[mi][2 * np],     a[mi], bt);
                    mma_f16(acc[mi][2 * np + 1], a[mi], bt + 2);
                }
            }
        }
        if (t + 1 < T) {
            *(uint4*)&As[nxt][lrow][lh]     = ra[0];
            *(uint4*)&As[nxt][lrow][lh + 8] = ra[1];
            *(uint4*)&Bs[nxt][lrow][lh]     = rb[0];
            *(uint4*)&Bs[nxt][lrow][lh + 8] = rb[1];
        }
        __syncthreads();
    }

    // ---------------- epilogue ----------------
    float*  Cf = (float*)Cv;
    __half* Ch = (__half*)Cv;
#pragma unroll
    for (int mi = 0; mi < 2; mi++) {
        const int r0 = bm + wm * 32 + mi * 16 + g;
#pragma unroll
        for (int ni = 0; ni < 8; ni++) {
            const int c0 = bn + wn * 64 + ni * 8 + 2 * tig;
            const float b0 = bias[c0], b1 = bias[c0 + 1];
            float v00 = acc[mi][ni][0] * iscl + b0, v01 = acc[mi][ni][1] * iscl + b1;
            float v10 = acc[mi][ni][2] * iscl + b0, v11 = acc[mi][ni][3] * iscl + b1;
            if (EPI == 2) {
                const int hh = c0 >> 6, rr = c0 & 63, jj = rr >> 1;
                float fr = __expf(-(float)jj * 0.28782313663258307f); // ln(1e4)/32
                float sn, cs;
                sincosf((float)hh * fr, &sn, &cs);
                float w00 = (v00 * cs - v01 * sn) * oscl, w01 = (v00 * sn + v01 * cs) * oscl;
                float w10 = (v10 * cs - v11 * sn) * oscl, w11 = (v10 * sn + v11 * cs) * oscl;
                size_t i0 = ((size_t)r0 * NH + hh) * DT + HD + rr;
                size_t i1 = ((size_t)(r0 + 8) * NH + hh) * DT + HD + rr;
                sth2(&Ch[i0], w00, w01);
                sth2(&Ch[i1], w10, w11);
            } else {
                v00 *= oscl; v01 *= oscl; v10 *= oscl; v11 *= oscl;
                if (EPI == 1) {
                    const int hh = c0 >> 7, dd = c0 & 127;
                    size_t i0 = ((size_t)r0 * NH + hh) * DT + dd;
                    size_t i1 = ((size_t)(r0 + 8) * NH + hh) * DT + dd;
                    sth2(&Ch[i0], v00, v01);
                    sth2(&Ch[i1], v10, v11);
                } else if (OUTH) {
                    sth2(&Ch[(size_t)r0 * N + c0], v00, v01);
                    sth2(&Ch[(size_t)(r0 + 8) * N + c0], v10, v11);
                } else {
                    *(float2*)&Cf[(size_t)r0 * N + c0]       = make_float2(v00, v01);
                    *(float2*)&Cf[(size_t)(r0 + 8) * N + c0] = make_float2(v10, v11);
                }
            }
        }
    }
}

// ---------------------------------------------------------------------------
// Flash attention, fp16 mma + ldmatrix. Block = (head, 128 q-rows), 256 thr.
// Q/K scaled by SCL_KQ each, V by SCL_V (producers); SCALE compensates Q*K.
// ctx output carries SCL_V (final GEMM divides). Softmax in fp32.
// ---------------------------------------------------------------------------
#define QLD 200
#define KLD 200
#define VTLD 64
#define PLD 72
#define ATT_H (128*QLD + 64*KLD + 128*VTLD + 128*PLD)
#define ATT_BYTES (ATT_H * 2)

__global__ void __launch_bounds__(256)
attn_h(const __half* __restrict__ Qg, const __half* __restrict__ Kg,
       const __half* __restrict__ Vg, __half* __restrict__ ctxg)
{
    extern __shared__ __half sh[];
    __half* Qs = sh;                    // [128][200]
    __half* Ks = Qs + 128 * QLD;        // [64][200]
    __half* Vt = Ks + 64 * KLD;         // [128][64]  d-major, swizzled 16B units
    __half* Ps = Vt + 128 * VTLD;       // [128][72]

    const int tid  = threadIdx.x;
    const int warp = tid >> 5, lane = tid & 31;
    const int g    = lane >> 2, tig = lane & 3;
    const int h    = blockIdx.y;
    const int q0   = blockIdx.x * 128;

    const int a_row = lane & 15;
    const int a_c   = 8 * (lane >> 4);
    const int b_row = ((lane >> 4) << 3) + (lane & 7);
    const int b_c   = 8 * ((lane >> 3) & 1);
    const int b_kh  = (lane >> 3) & 1;

    // ---- Q tile: 128 x 192 halves = 1536 uint4 ----
#pragma unroll
    for (int i = 0; i < 6; i++) {
        int idx = tid + 256 * i;
        int row = idx / 12, u = idx % 12;
        *(uint4*)&Qs[row * QLD + u * 16] =
            *(const uint4*)(Qg + (size_t)(q0 + row) * (NH * DT) + h * DT + u * 16);
    }

    float m_[2] = {-1e30f, -1e30f}, l_[2] = {0.f, 0.f};
    float o[16][4];
#pragma unroll
    for (int ni = 0; ni < 16; ni++)
#pragma unroll
        for (int e = 0; e < 4; e++) o[ni][e] = 0.f;

    // 1/sqrt(192) compensated for K,Q scaling (SCL_KQ^2)
    const float SCALE = 0.07216878364870323f / (SCL_KQ * SCL_KQ);
    const int rw = warp * 16;
    const int prow = rw + g;

    for (int kt = 0; kt < SEQ / 64; kt++) {
        const int kbase = kt * 64;
        // ---- K tile: 64 x 192 halves = 768 uint4 ----
#pragma unroll
        for (int i = 0; i < 3; i++) {
            int idx = tid + 256 * i;
            int row = idx / 12, u = idx % 12;
            *(uint4*)&Ks[row * KLD + u * 16] =
                *(const uint4*)(Kg + (size_t)(kbase + row) * (NH * DT) + h * DT + u * 16);
        }
        // ---- V tile transposed: 64 k-rows x 128 d ----
#pragma unroll
        for (int i = 0; i < 4; i++) {
            int idx = tid + 256 * i;          // 0..1023
            int k = idx >> 4, d0 = (idx & 15) * 8;
            uint4 v = *(const uint4*)(Vg + (size_t)(kbase + k) * (NH * HD) + h * HD + d0);
            __half tmp[8];
            *(uint4*)tmp = v;
            const int ku = k >> 3, kl = k & 7;
#pragma unroll
            for (int j = 0; j < 8; j++)
                Vt[(d0 + j) * VTLD + ((ku ^ j) << 3) + kl] = tmp[j];
        }
        __syncthreads();

        // ---- S = Q K^T : 12 k16 steps ----
        float s[8][4];
#pragma unroll
        for (int ni = 0; ni < 8; ni++)
#pragma unroll
            for (int e = 0; e < 4; e++) s[ni][e] = 0.f;

#pragma unroll
        for (int kk = 0; kk < 12; kk++) {
            const int k16 = kk * 16;
            unsigned a[4];
            ldsm4(a, &Qs[(rw + a_row) * QLD + k16 + a_c]);
#pragma unroll
            for (int np = 0; np < 4; np++) {
                unsigned bt[4];
                ldsm4(bt, &Ks[(np * 16 + b_row) * KLD + k16 + b_c]);
                mma_f16(s[2 * np],     a, bt);
                mma_f16(s[2 * np + 1], a, bt + 2);
            }
        }

        // ---- online softmax (rows prow / prow+8) ----
        float tm0 = -1e30f, tm1 = -1e30f;
#pragma unroll
        for (int ni = 0; ni < 8; ni++) {
#pragma unroll
            for (int e = 0; e < 4; e++) s[ni][e] *= SCALE;
            tm0 = fmaxf(tm0, fmaxf(s[ni][0], s[ni][1]));
            tm1 = fmaxf(tm1, fmaxf(s[ni][2], s[ni][3]));
        }
        tm0 = fmaxf(tm0, __shfl_xor_sync(0xffffffffu, tm0, 1, 4));
        tm0 = fmaxf(tm0, __shfl_xor_sync(0xffffffffu, tm0, 2, 4));
        tm1 = fmaxf(tm1, __shfl_xor_sync(0xffffffffu, tm1, 1, 4));
        tm1 = fmaxf(tm1, __shfl_xor_sync(0xffffffffu, tm1, 2, 4));

        float mn0 = fmaxf(m_[0], tm0), mn1 = fmaxf(m_[1], tm1);
        float corr0 = __expf(m_[0] - mn0), corr1 = __expf(m_[1] - mn1);
        m_[0] = mn0; m_[1] = mn1;

        float rs0 = 0.f, rs1 = 0.f;
#pragma unroll
        for (int ni = 0; ni < 8; ni++) {
            s[ni][0] = __expf(s[ni][0] - mn0);
            s[ni][1] = __expf(s[ni][1] - mn0);
            s[ni][2] = __expf(s[ni][2] - mn1);
            s[ni][3] = __expf(s[ni][3] - mn1);
            rs0 += s[ni][0] + s[ni][1];
            rs1 += s[ni][2] + s[ni][3];
        }
        rs0 += __shfl_xor_sync(0xffffffffu, rs0, 1, 4);
        rs0 += __shfl_xor_sync(0xffffffffu, rs0, 2, 4);
        rs1 += __shfl_xor_sync(0xffffffffu, rs1, 1, 4);
        rs1 += __shfl_xor_sync(0xffffffffu, rs1, 2, 4);
        l_[0] = l_[0] * corr0 + rs0;
        l_[1] = l_[1] * corr1 + rs1;

        // ---- stage P (half, warp-local rows), rescale ctx ----
#pragma unroll
        for (int ni = 0; ni < 8; ni++) {
            sth2(&Ps[prow * PLD + ni * 8 + 2 * tig], s[ni][0], s[ni][1]);
            sth2(&Ps[(prow + 8) * PLD + ni * 8 + 2 * tig], s[ni][2], s[ni][3]);
        }
#pragma unroll
        for (int ni = 0; ni < 16; ni++) {
            o[ni][0] *= corr0; o[ni][1] *= corr0;
            o[ni][2] *= corr1; o[ni][3] *= corr1;
        }
        __syncwarp();

        // ---- ctx += P @ V : 4 k16 steps ----
#pragma unroll
        for (int ks = 0; ks < 4; ks++) {
            unsigned a[4];
            ldsm4(a, &Ps[(rw + a_row) * PLD + ks * 16 + a_c]);
#pragma unroll
            for (int np = 0; np < 8; np++) {
                const int d = np * 16 + b_row;
                unsigned bt[4];
                ldsm4(bt, &Vt[d * VTLD + (((2 * ks + b_kh) ^ (d & 7)) << 3)]);
                mma_f16(o[2 * np],     a, bt);
                mma_f16(o[2 * np + 1], a, bt + 2);
            }
        }
        __syncthreads();
    }

    // ---- finalize & store (half; carries SCL_V) ----
    const float inv0 = 1.0f / l_[0], inv1 = 1.0f / l_[1];
    const int r0 = q0 + rw + g;
#pragma unroll
    for (int ni = 0; ni < 16; ni++) {
        const int col = ni * 8 + 2 * tig;
        sth2(&ctxg[(size_t)r0 * (NH * HD) + h * HD + col],
             o[ni][0] * inv0, o[ni][1] * inv0);
        sth2(&ctxg[(size_t)(r0 + 8) * (NH * HD) + h * HD + col],
             o[ni][2] * inv1, o[ni][3] * inv1);
    }
}

// ---------------------------------------------------------------------------
extern "C" void kernel_launch(void* const* d_in, const int* in_sizes, int n_in,
                              void* d_out, int out_size)
{
    (void)in_sizes; (void)n_in; (void)out_size;
    const float* x   = (const float*)d_in[0];
    const float* kdw = (const float*)d_in[1];
    const float* kdb = (const float*)d_in[2];
    const float* kuw = (const float*)d_in[3];
    const float* kub = (const float*)d_in[4];
    const float* vuw = (const float*)d_in[5];
    const float* vub = (const float*)d_in[6];
    const float* krw = (const float*)d_in[7];
    const float* krb = (const float*)d_in[8];
    const float* qdw = (const float*)d_in[9];
    const float* qdb = (const float*)d_in[10];
    const float* quw = (const float*)d_in[11];
    const float* qub = (const float*)d_in[12];
    const float* qrw = (const float*)d_in[13];
    const float* qrb = (const float*)d_in[14];
    const float* ow  = (const float*)d_in[15];
    const float* ob  = (const float*)d_in[16];
    float* out = (float*)d_out;

    __half *kvc, *qc, *Kb, *Qb, *Vb, *ctx;
    cudaGetSymbolAddress((void**)&kvc, g_kvc);
    cudaGetSymbolAddress((void**)&qc,  g_qc);
    cudaGetSymbolAddress((void**)&Kb,  g_K);
    cudaGetSymbolAddress((void**)&Qb,  g_Q);
    cudaGetSymbolAddress((void**)&Vb,  g_V);
    cudaGetSymbolAddress((void**)&ctx, g_ctx);

    dim3 blk(256);

    // down-projections: A = x (float), unscaled outputs
    gemm_h<0, false, true><<<dim3(KVC / 128, SEQ / 128), blk>>>(x, kdw, kdb, kvc, KVC, HID, 1.f, 1.f);
    gemm_h<0, false, true><<<dim3(QC / 128, SEQ / 128), blk>>>(x, qdw, qdb, qc, QC, HID, 1.f, 1.f);
    // up-projections: K,Q scaled by SCL_KQ; V by SCL_V
    gemm_h<1, true, true><<<dim3(2048 / 128, SEQ / 128), blk>>>(kvc, kuw, kub, Kb, 2048, KVC, 1.f, SCL_KQ);
    gemm_h<0, true, true><<<dim3(2048 / 128, SEQ / 128), blk>>>(kvc, vuw, vub, Vb, 2048, KVC, 1.f, SCL_V);
    gemm_h<2, true, true><<<dim3(1024 / 128, SEQ / 128), blk>>>(kvc, krw, krb, Kb, 1024, KVC, 1.f, SCL_KQ);
    gemm_h<1, true, true><<<dim3(2048 / 128, SEQ / 128), blk>>>(qc, quw, qub, Qb, 2048, QC, 1.f, SCL_KQ);
    gemm_h<2, true, true><<<dim3(1024 / 128, SEQ / 128), blk>>>(qc, qrw, qrb, Qb, 1024, QC, 1.f, SCL_KQ);

    cudaFuncSetAttribute(attn_h, cudaFuncAttributeMaxDynamicSharedMemorySize, ATT_BYTES);
    attn_h<<<dim3(SEQ / 128, NH), dim3(256), ATT_BYTES>>>(Qb, Kb, Vb, ctx);

    // final projection: A = ctx (half, carries SCL_V) -> divide; output float
    gemm_h<0, true, false><<<dim3(2048 / 128, SEQ / 128), blk>>>(ctx, ow, ob, out, HID, 2048, 1.f / SCL_V, 1.f);
}